// round 9
// baseline (speedup 1.0000x reference)
#include <cuda_runtime.h>

// DepthwiseRREUp: groups=C*G conv_transpose2d, kernel=stride=2, pad=0.
// out[b,c,g, 2i+di, 2j+dj] = x[b,c,g,i,j] * rot90(dw[c], g)[di][dj]
//
// x:  [B=8, C=256, G=4, H=64, W=64] fp32     (128 MiB, read once)
// dw: [C=256, 1, 2, 2] fp32                  (cache-resident)
// out:[B, C, G, 128, 128] fp32               (512 MiB, written once)
//
// Mapping: lane = output quad index q (32 quads = one 128-float output row),
// thread covers 8 consecutive output rows (4 input rows) at quad q.
// Per thread: 4x LDG.64 + 8x STG.128, all independent (MLP=12).
// Warp-level: every LDG is 256 B contiguous, every STG is 512 B contiguous,
// sequential across warps -> DRAM-page friendly, fully-filled 128 B lines.
// R8 profile: DRAM 78.6%, everything else idle -> latency-exposed; doubling
// per-thread in-flight bytes is the remaining lever.

__global__ void __launch_bounds__(256)
DepthwiseRREUp_40106404610493_kernel(const float2* __restrict__ x2,
                                     const float4* __restrict__ dw4,  // [C] of (a,b,c,d)
                                     float4* __restrict__ out4,
                                     int nthreads) {
    int t = blockIdx.x * blockDim.x + threadIdx.x;
    if (t >= nthreads) return;

    int q     = t & 31;          // quad within row == lane
    int rg    = t >> 5;          // row-group: 8 output rows
    int oi0   = (rg & 15) << 3;  // first output row (0..120, step 8)
    int plane = rg >> 4;         // linear (b,c,g)
    int g     = plane & 3;       // warp-uniform
    int c     = (plane >> 2) & 255;

    // Input rows oi0/2 .. oi0/2+3. Input plane = 2048 float2, 32 per row.
    const float2* xp = x2 + plane * 2048 + (oi0 >> 1) * 32 + q;
    float2 x0 = __ldcs(xp);
    float2 x1 = __ldcs(xp + 32);
    float2 x2v = __ldcs(xp + 64);
    float2 x3 = __ldcs(xp + 96);

    float4 w = dw4[c];  // a=w.x b=w.y c=w.z d=w.w (row-major 2x2)

    // numpy rot90 (CCW) k=g of [[a,b],[c,d]]:
    //   g=0: a b / c d    g=1: b d / a c
    //   g=2: d c / b a    g=3: c a / d b
    float f00, f01, f10, f11;
    switch (g) {
        case 0:  f00 = w.x; f01 = w.y; f10 = w.z; f11 = w.w; break;
        case 1:  f00 = w.y; f01 = w.w; f10 = w.x; f11 = w.z; break;
        case 2:  f00 = w.w; f01 = w.z; f10 = w.y; f11 = w.x; break;
        default: f00 = w.z; f01 = w.x; f10 = w.w; f11 = w.y; break;
    }

    // Output plane = 4096 float4, 32 per row.
    float4* op = out4 + plane * 4096 + oi0 * 32 + q;
    __stcs(op,       make_float4(x0.x * f00, x0.x * f01, x0.y * f00, x0.y * f01));
    __stcs(op + 32,  make_float4(x0.x * f10, x0.x * f11, x0.y * f10, x0.y * f11));
    __stcs(op + 64,  make_float4(x1.x * f00, x1.x * f01, x1.y * f00, x1.y * f01));
    __stcs(op + 96,  make_float4(x1.x * f10, x1.x * f11, x1.y * f10, x1.y * f11));
    __stcs(op + 128, make_float4(x2v.x * f00, x2v.x * f01, x2v.y * f00, x2v.y * f01));
    __stcs(op + 160, make_float4(x2v.x * f10, x2v.x * f11, x2v.y * f10, x2v.y * f11));
    __stcs(op + 192, make_float4(x3.x * f00, x3.x * f01, x3.y * f00, x3.y * f01));
    __stcs(op + 224, make_float4(x3.x * f10, x3.x * f11, x3.y * f10, x3.y * f11));
}

extern "C" void kernel_launch(void* const* d_in, const int* in_sizes, int n_in,
                              void* d_out, int out_size) {
    const float2* x2  = (const float2*)d_in[0];
    const float4* dw4 = (const float4*)d_in[1];
    float4* out4      = (float4*)d_out;

    int nthreads = out_size / 32;                 // 8 output quads per thread
    int threads = 256;
    int blocks = (nthreads + threads - 1) / threads;
    DepthwiseRREUp_40106404610493_kernel<<<blocks, threads>>>(x2, dw4, out4, nthreads);
}